// round 3
// baseline (speedup 1.0000x reference)
#include <cuda_runtime.h>
#include <cstdint>

#define BM 64
#define NTHREADS 256

// ---------------- scratch (device globals; no allocation allowed) ----------------
__device__ __align__(16) float g_O0[38400000];   // 300000 * 128
__device__ __align__(16) float g_O1[38400000];   // 300000 * 128
__device__ __align__(16) float g_O2[38400000];   // 200000 * 192
__device__ __align__(16) float g_exps[12800000]; // 200000 * 64
__device__ unsigned g_max_bits;
__device__ int g_idx64;  // 1 if index buffers are int64, 0 if int32

__device__ __forceinline__ void atomicMaxF(float val) {
    if (val >= 0.f) atomicMax((int*)&g_max_bits, __float_as_int(val));
    else            atomicMin(&g_max_bits, (unsigned)__float_as_int(val));
}

__device__ __forceinline__ int load_idx(const void* idx, long long flat, int is64) {
    if (is64) return (int)__ldg(reinterpret_cast<const long long*>(idx) + flat);
    return __ldg(reinterpret_cast<const int*>(idx) + flat);
}

// ---------------- dtype probe: int64 buffers of small values have zero odd words ----------------
__global__ void detect_kernel(const int* __restrict__ i0) {
    if (threadIdx.x == 0 && blockIdx.x == 0) {
        int is64 = 1;
        #pragma unroll
        for (int k = 1; k < 32; k += 2)
            if (__ldg(i0 + k) != 0) { is64 = 0; break; }
        g_idx64 = is64;
    }
}

// ---------------- shared tiled GEMM core ----------------
// Xs: smem [64][K] row-major (stride K). Wg: global [NCOL][K] row-major.
// acc[i][j] += sum_k Xs[ty+16i][k] * Wg[tx+16j][k].
template<int K, int NCOL>
__device__ __forceinline__ void gemm_tile(const float* __restrict__ Xs,
                                          float* __restrict__ Ws,
                                          const float* __restrict__ Wg,
                                          float (&acc)[4][NCOL / 16], int tid) {
    const int tx = tid & 15, ty = tid >> 4;
    constexpr int NJ = NCOL / 16;
    constexpr int LD = NCOL + 1;
    for (int k0 = 0; k0 < K; k0 += 16) {
        __syncthreads(); // protect Ws reuse (also orders producer smem writes on first iter)
        #pragma unroll
        for (int u = tid; u < 16 * NCOL; u += NTHREADS) {
            int j = u >> 4, kk = u & 15;
            Ws[kk * LD + j] = __ldg(Wg + j * K + k0 + kk);
        }
        __syncthreads();
        #pragma unroll
        for (int kk = 0; kk < 16; ++kk) {
            float a[4], b[NJ];
            #pragma unroll
            for (int i = 0; i < 4; ++i) a[i] = Xs[(ty + 16 * i) * K + k0 + kk];
            #pragma unroll
            for (int j = 0; j < NJ; ++j) b[j] = Ws[kk * LD + tx + 16 * j];
            #pragma unroll
            for (int i = 0; i < 4; ++i)
                #pragma unroll
                for (int j = 0; j < NJ; ++j)
                    acc[i][j] = fmaf(a[i], b[j], acc[i][j]);
        }
    }
}

// ---------------- per-relation fused MLP: gather -> relu(X@W1^T+b1) -> @W2^T+b2 ----------------
template<int A>
__global__ void __launch_bounds__(NTHREADS)
rel_kernel(const float* __restrict__ ns, const void* __restrict__ idx,
           const float* __restrict__ w1, const float* __restrict__ b1,
           const float* __restrict__ w2, const float* __restrict__ b2,
           int T, int which) {
    constexpr int D = A * 64;
    constexpr int NJ = D / 16;
    extern __shared__ float smem[];
    float* Xs  = smem;                 // [64][D], later reused as H
    float* Ws  = Xs + BM * D;          // [16][D+1]
    float* red = Ws + 16 * (D + 1);    // [8]
    int*  s_idx = (int*)(red + 8);     // [64*A]
    float* Oout = (which == 0) ? g_O0 : (which == 1) ? g_O1 : g_O2;

    const int tid = threadIdx.x;
    const int tx = tid & 15, ty = tid >> 4;
    const int m0 = blockIdx.x * BM;
    const int is64 = g_idx64;

    // cache tuple indices
    for (int e = tid; e < BM * A; e += NTHREADS) {
        long long flat = (long long)m0 * A + e;
        s_idx[e] = (flat < (long long)T * A) ? load_idx(idx, flat, is64) : -1;
    }
    __syncthreads();
    // gather: 16 consecutive threads copy one 64-float node row (256B coalesced)
    for (int u = tid; u < BM * A * 16; u += NTHREADS) {
        int pair = u >> 4;    // row*A + slot  (Xs offset = pair*64 since D = A*64)
        int v = u & 15;
        int node = s_idx[pair];
        float4 val = make_float4(0.f, 0.f, 0.f, 0.f);
        if (node >= 0)
            val = __ldg(reinterpret_cast<const float4*>(ns + (long long)node * 64) + v);
        reinterpret_cast<float4*>(Xs + pair * 64)[v] = val;
    }

    float acc[4][NJ];
    #pragma unroll
    for (int i = 0; i < 4; ++i)
        #pragma unroll
        for (int j = 0; j < NJ; ++j) acc[i][j] = 0.f;

    gemm_tile<D, D>(Xs, Ws, w1, acc, tid);
    __syncthreads(); // all reads of Xs done before overwrite with H
    #pragma unroll
    for (int j = 0; j < NJ; ++j) {
        int c = tx + 16 * j;
        float bb = __ldg(b1 + c);
        #pragma unroll
        for (int i = 0; i < 4; ++i) {
            float h = acc[i][j] + bb;
            Xs[(ty + 16 * i) * D + c] = h > 0.f ? h : 0.f;
            acc[i][j] = 0.f;
        }
    }
    gemm_tile<D, D>(Xs, Ws, w2, acc, tid);

    float lmax = __int_as_float(0xff800000); // -inf
    #pragma unroll
    for (int j = 0; j < NJ; ++j) {
        int c = tx + 16 * j;
        float bb = __ldg(b2 + c);
        #pragma unroll
        for (int i = 0; i < 4; ++i) {
            int m = m0 + ty + 16 * i;
            if (m < T) {
                float o = acc[i][j] + bb;
                Oout[(long long)m * D + c] = o;
                lmax = fmaxf(lmax, o);
            }
        }
    }
    // block max -> single atomic
    #pragma unroll
    for (int off = 16; off; off >>= 1)
        lmax = fmaxf(lmax, __shfl_xor_sync(0xffffffffu, lmax, off));
    if ((tid & 31) == 0) red[tid >> 5] = lmax;
    __syncthreads();
    if (tid < 8) {
        float v = red[tid];
        #pragma unroll
        for (int off = 4; off; off >>= 1)
            v = fmaxf(v, __shfl_xor_sync(0xffu, v, off, 8));
        if (tid == 0) atomicMaxF(v);
    }
}

// ---------------- init exps + global max ----------------
__global__ void __launch_bounds__(NTHREADS) init_kernel() {
    int t = blockIdx.x * NTHREADS + threadIdx.x;
    if (t == 0) g_max_bits = 0xff800000u; // -inf
    if (t < 12800000 / 4)
        reinterpret_cast<float4*>(g_exps)[t] =
            make_float4(1e-16f, 1e-16f, 1e-16f, 1e-16f);
}

// ---------------- scatter exp(8*(o - gmax)) into g_exps ----------------
__global__ void __launch_bounds__(NTHREADS)
scatter_kernel(const void* __restrict__ idx, int nflat, int which) {
    const float* O = (which == 0) ? g_O0 : (which == 1) ? g_O1 : g_O2;
    const float gmax = __uint_as_float(g_max_bits);
    const int is64 = g_idx64;
    const int total = nflat * 16;
    for (int t = blockIdx.x * NTHREADS + threadIdx.x; t < total;
         t += gridDim.x * NTHREADS) {
        int row = t >> 4;
        int col = (t & 15) << 2;
        int node = load_idx(idx, row, is64);
        float4 v = __ldg(reinterpret_cast<const float4*>(O + ((long long)row << 6) + col));
        float4 e;
        e.x = __expf(8.f * (v.x - gmax));
        e.y = __expf(8.f * (v.y - gmax));
        e.z = __expf(8.f * (v.z - gmax));
        e.w = __expf(8.f * (v.w - gmax));
        float* p = g_exps + ((long long)node << 6) + col;
        asm volatile("red.global.add.v4.f32 [%0], {%1,%2,%3,%4};"
                     :: "l"(p), "f"(e.x), "f"(e.y), "f"(e.z), "f"(e.w) : "memory");
    }
}

// ---------------- final update MLP: relu(cat@u_w1^T+b1)@u_w2^T+b2 ----------------
__global__ void __launch_bounds__(NTHREADS)
update_kernel(const float* __restrict__ ns,
              const float* __restrict__ uw1, const float* __restrict__ ub1,
              const float* __restrict__ uw2, const float* __restrict__ ub2,
              float* __restrict__ out, int Nn) {
    extern __shared__ float smem[];
    float* Cs = smem;            // [64][128]  (cat, later H)
    float* Ws = Cs + BM * 128;   // [16][129]
    const int tid = threadIdx.x;
    const int tx = tid & 15, ty = tid >> 4;
    const int n0 = blockIdx.x * BM;
    float gmax = __uint_as_float(g_max_bits);

    for (int u = tid; u < BM * 128; u += NTHREADS) {
        int row = u >> 7;
        int c = u & 127;
        int n = n0 + row;
        float val = 0.f;
        if (n < Nn) {
            if (c < 64) val = 0.125f * __logf(g_exps[(long long)n * 64 + c]) + gmax;
            else        val = __ldg(ns + (long long)n * 64 + (c - 64));
        }
        Cs[u] = val;
    }
    float acc[4][8];
    #pragma unroll
    for (int i = 0; i < 4; ++i)
        #pragma unroll
        for (int j = 0; j < 8; ++j) acc[i][j] = 0.f;
    gemm_tile<128, 128>(Cs, Ws, uw1, acc, tid);
    __syncthreads();
    #pragma unroll
    for (int j = 0; j < 8; ++j) {
        int c = tx + 16 * j;
        float bb = __ldg(ub1 + c);
        #pragma unroll
        for (int i = 0; i < 4; ++i) {
            float h = acc[i][j] + bb;
            Cs[(ty + 16 * i) * 128 + c] = h > 0.f ? h : 0.f;
        }
    }
    float acc2[4][4];
    #pragma unroll
    for (int i = 0; i < 4; ++i)
        #pragma unroll
        for (int j = 0; j < 4; ++j) acc2[i][j] = 0.f;
    gemm_tile<128, 64>(Cs, Ws, uw2, acc2, tid);
    #pragma unroll
    for (int j = 0; j < 4; ++j) {
        int c = tx + 16 * j;
        float bb = __ldg(ub2 + c);
        #pragma unroll
        for (int i = 0; i < 4; ++i) {
            int n = n0 + ty + 16 * i;
            if (n < Nn) out[(long long)n * 64 + c] = acc2[i][j] + bb;
        }
    }
}

// ---------------- host ----------------
extern "C" void kernel_launch(void* const* d_in, const int* in_sizes, int n_in,
                              void* d_out, int out_size) {
    const float* ns  = (const float*)d_in[0];
    const void*  i0  = d_in[1];
    const void*  i1  = d_in[2];
    const void*  i2  = d_in[3];
    const float* r0w1 = (const float*)d_in[4];
    const float* r0b1 = (const float*)d_in[5];
    const float* r0w2 = (const float*)d_in[6];
    const float* r0b2 = (const float*)d_in[7];
    const float* r1w1 = (const float*)d_in[8];
    const float* r1b1 = (const float*)d_in[9];
    const float* r1w2 = (const float*)d_in[10];
    const float* r1b2 = (const float*)d_in[11];
    const float* r2w1 = (const float*)d_in[12];
    const float* r2b1 = (const float*)d_in[13];
    const float* r2w2 = (const float*)d_in[14];
    const float* r2b2 = (const float*)d_in[15];
    const float* uw1  = (const float*)d_in[16];
    const float* ub1  = (const float*)d_in[17];
    const float* uw2  = (const float*)d_in[18];
    const float* ub2  = (const float*)d_in[19];
    float* out = (float*)d_out;

    const int T0 = in_sizes[1] / 2;
    const int T1 = in_sizes[2] / 2;
    const int T2 = in_sizes[3] / 3;
    const int Nn = in_sizes[0] / 64;

    const int smem2 = (BM * 128 + 16 * 129 + 8 + BM * 2) * 4;
    const int smem3 = (BM * 192 + 16 * 193 + 8 + BM * 3) * 4;
    const int smemU = (BM * 128 + 16 * 129) * 4;

    static bool attr_done = false;
    if (!attr_done) {
        cudaFuncSetAttribute(rel_kernel<2>, cudaFuncAttributeMaxDynamicSharedMemorySize, smem2);
        cudaFuncSetAttribute(rel_kernel<3>, cudaFuncAttributeMaxDynamicSharedMemorySize, smem3);
        cudaFuncSetAttribute(update_kernel, cudaFuncAttributeMaxDynamicSharedMemorySize, smemU);
        attr_done = true;
    }

    detect_kernel<<<1, 32>>>((const int*)i0);
    init_kernel<<<(12800000 / 4 + NTHREADS - 1) / NTHREADS, NTHREADS>>>();

    rel_kernel<2><<<(T0 + BM - 1) / BM, NTHREADS, smem2>>>(ns, i0, r0w1, r0b1, r0w2, r0b2, T0, 0);
    rel_kernel<2><<<(T1 + BM - 1) / BM, NTHREADS, smem2>>>(ns, i1, r1w1, r1b1, r1w2, r1b2, T1, 1);
    rel_kernel<3><<<(T2 + BM - 1) / BM, NTHREADS, smem3>>>(ns, i2, r2w1, r2b1, r2w2, r2b2, T2, 2);

    scatter_kernel<<<(T0 * 2 * 16 + NTHREADS - 1) / NTHREADS, NTHREADS>>>(i0, T0 * 2, 0);
    scatter_kernel<<<(T1 * 2 * 16 + NTHREADS - 1) / NTHREADS, NTHREADS>>>(i1, T1 * 2, 1);
    scatter_kernel<<<(T2 * 3 * 16 + NTHREADS - 1) / NTHREADS, NTHREADS>>>(i2, T2 * 3, 2);

    update_kernel<<<(Nn + BM - 1) / BM, NTHREADS, smemU>>>(ns, uw1, ub1, uw2, ub2, out, Nn);
}

// round 8
// speedup vs baseline: 1.0703x; 1.0703x over previous
#include <cuda_runtime.h>
#include <cstdint>

// ---------------- scratch (device globals; no allocation allowed) ----------------
__device__ __align__(16) float g_exps[12800000]; // 200000 * 64  (sum of exp(8*o))
__device__ unsigned g_max_bits;
__device__ int g_idx64;  // 1 if index buffers are int64, 0 if int32

__device__ __forceinline__ void atomicMaxF(float val) {
    if (val >= 0.f) atomicMax((int*)&g_max_bits, __float_as_int(val));
    else            atomicMin(&g_max_bits, (unsigned)__float_as_int(val));
}

__device__ __forceinline__ int load_idx(const void* idx, long long flat, int is64) {
    if (is64) return (int)__ldg(reinterpret_cast<const long long*>(idx) + flat);
    return __ldg(reinterpret_cast<const int*>(idx) + flat);
}

// ---------------- dtype probe: int64 buffers of small values have zero odd words ----------------
__global__ void detect_kernel(const int* __restrict__ i0) {
    if (threadIdx.x == 0 && blockIdx.x == 0) {
        int is64 = 1;
        #pragma unroll
        for (int k = 1; k < 32; k += 2)
            if (__ldg(i0 + k) != 0) { is64 = 0; break; }
        g_idx64 = is64;
    }
}

// ---------------- shared tiled GEMM core ----------------
// Xs: smem [BM][LDX]. Wg: global [NCOL][K] row-major.
// acc[i][j] += sum_k Xs[ty+TY*i][k] * Wg[tx+16j][k].
template<int K, int LDX, int NCOL, int NT, int RI>
__device__ __forceinline__ void gemm_tile(const float* __restrict__ Xs,
                                          float* __restrict__ Ws,
                                          const float* __restrict__ Wg,
                                          float (&acc)[RI][NCOL / 16], int tid) {
    const int tx = tid & 15, ty = tid >> 4;
    constexpr int TY = NT / 16;
    constexpr int NJ = NCOL / 16;
    constexpr int LD = NCOL + 1;
    for (int k0 = 0; k0 < K; k0 += 16) {
        __syncthreads(); // protect Ws reuse (also orders producer smem writes on first iter)
        #pragma unroll
        for (int u = tid; u < 16 * NCOL; u += NT) {
            int j = u >> 4, kk = u & 15;
            Ws[kk * LD + j] = __ldg(Wg + j * K + k0 + kk);
        }
        __syncthreads();
        #pragma unroll
        for (int kk = 0; kk < 16; ++kk) {
            float a[RI], b[NJ];
            #pragma unroll
            for (int i = 0; i < RI; ++i) a[i] = Xs[(ty + TY * i) * LDX + k0 + kk];
            #pragma unroll
            for (int j = 0; j < NJ; ++j) b[j] = Ws[kk * LD + tx + 16 * j];
            #pragma unroll
            for (int i = 0; i < RI; ++i)
                #pragma unroll
                for (int j = 0; j < NJ; ++j)
                    acc[i][j] = fmaf(a[i], b[j], acc[i][j]);
        }
    }
}

// ---------------- fused per-relation: gather -> MLP -> exp(8*o) scatter-add ----------------
// BM = 128 tuples per block.
template<int A, int NT, int RI, int MINB>
__global__ void __launch_bounds__(NT, MINB)
rel_kernel(const float* __restrict__ ns, const void* __restrict__ idx,
           const float* __restrict__ w1, const float* __restrict__ b1,
           const float* __restrict__ w2, const float* __restrict__ b2,
           int T) {
    constexpr int BM = 128;
    constexpr int D = A * 64;
    constexpr int LDX = D + 4;
    constexpr int NJ = D / 16;
    constexpr int TY = NT / 16;
    constexpr int NW = NT / 32;
    extern __shared__ float smem[];
    float* Xs  = smem;                  // [BM][LDX]  (X, then H, then O)
    float* Ws  = Xs + BM * LDX;         // [16][D+1]
    float* red = Ws + 16 * (D + 1);     // [NW]
    int* s_idx = (int*)(red + NW);      // [BM*A]

    const int tid = threadIdx.x;
    const int tx = tid & 15, ty = tid >> 4;
    const int m0 = blockIdx.x * BM;
    const int is64 = g_idx64;

    // cache tuple indices
    for (int e = tid; e < BM * A; e += NT) {
        long long flat = (long long)m0 * A + e;
        s_idx[e] = (flat < (long long)T * A) ? load_idx(idx, flat, is64) : -1;
    }
    __syncthreads();
    // gather: 16 consecutive threads copy one 64-float node row
    for (int u = tid; u < BM * A * 16; u += NT) {
        int pair = u >> 4;           // row*A + slot
        int v = u & 15;
        int row = pair / A;
        int slot = pair - row * A;
        int node = s_idx[pair];
        float4 val = make_float4(0.f, 0.f, 0.f, 0.f);
        if (node >= 0)
            val = __ldg(reinterpret_cast<const float4*>(ns + (long long)node * 64) + v);
        reinterpret_cast<float4*>(Xs + row * LDX + slot * 64)[v] = val;
    }

    float acc[RI][NJ];
    #pragma unroll
    for (int i = 0; i < RI; ++i)
        #pragma unroll
        for (int j = 0; j < NJ; ++j) acc[i][j] = 0.f;

    gemm_tile<D, LDX, D, NT, RI>(Xs, Ws, w1, acc, tid);
    __syncthreads(); // all reads of Xs done before overwrite with H
    #pragma unroll
    for (int j = 0; j < NJ; ++j) {
        int c = tx + 16 * j;
        float bb = __ldg(b1 + c);
        #pragma unroll
        for (int i = 0; i < RI; ++i) {
            float h = acc[i][j] + bb;
            Xs[(ty + TY * i) * LDX + c] = h > 0.f ? h : 0.f;
            acc[i][j] = 0.f;
        }
    }
    gemm_tile<D, LDX, D, NT, RI>(Xs, Ws, w2, acc, tid);
    __syncthreads(); // all reads of H done before overwrite with O

    float lmax = __int_as_float(0xff800000); // -inf
    #pragma unroll
    for (int j = 0; j < NJ; ++j) {
        int c = tx + 16 * j;
        float bb = __ldg(b2 + c);
        #pragma unroll
        for (int i = 0; i < RI; ++i) {
            int m = m0 + ty + TY * i;
            float o = acc[i][j] + bb;
            Xs[(ty + TY * i) * LDX + c] = o;
            if (m < T) lmax = fmaxf(lmax, o);
        }
    }
    __syncthreads();

    // vectorized exp + scatter-add of exp(8*o) (no max offset needed: it cancels)
    for (int u = tid; u < BM * A * 16; u += NT) {
        int pair = u >> 4;
        int v = u & 15;
        int node = s_idx[pair];
        if (node < 0) continue;
        int row = pair / A;
        int slot = pair - row * A;
        const float4* src = reinterpret_cast<const float4*>(Xs + row * LDX + slot * 64) + v;
        float4 o4 = *src;
        float4 e;
        e.x = __expf(8.f * o4.x);
        e.y = __expf(8.f * o4.y);
        e.z = __expf(8.f * o4.z);
        e.w = __expf(8.f * o4.w);
        float* p = g_exps + ((long long)node << 6) + (v << 2);
        asm volatile("red.global.add.v4.f32 [%0], {%1,%2,%3,%4};"
                     :: "l"(p), "f"(e.x), "f"(e.y), "f"(e.z), "f"(e.w) : "memory");
    }

    // block max -> single atomic (for the exact 1e-16 floor term later)
    #pragma unroll
    for (int off = 16; off; off >>= 1)
        lmax = fmaxf(lmax, __shfl_xor_sync(0xffffffffu, lmax, off));
    if ((tid & 31) == 0) red[tid >> 5] = lmax;
    __syncthreads();
    if (tid < NW) {
        float v = red[tid];
        #pragma unroll
        for (int off = NW / 2; off; off >>= 1)
            v = fmaxf(v, __shfl_xor_sync((1u << NW) - 1u, v, off, NW));
        if (tid == 0) atomicMaxF(v);
    }
}

// ---------------- init exps + global max ----------------
__global__ void __launch_bounds__(256) init_kernel() {
    int t = blockIdx.x * 256 + threadIdx.x;
    if (t == 0) g_max_bits = 0xff800000u; // -inf
    if (t < 12800000 / 4)
        reinterpret_cast<float4*>(g_exps)[t] = make_float4(0.f, 0.f, 0.f, 0.f);
}

// ---------------- final update MLP: relu(cat@u_w1^T+b1)@u_w2^T+b2 ----------------
// max_msg = 0.125*log(1e-16*e^{8g} + S) with S = sum exp(8*o)  (exact rewrite of ref)
__global__ void __launch_bounds__(256, 2)
update_kernel(const float* __restrict__ ns,
              const float* __restrict__ uw1, const float* __restrict__ ub1,
              const float* __restrict__ uw2, const float* __restrict__ ub2,
              float* __restrict__ out, int Nn) {
    constexpr int BM = 128, NT = 256, RI = 8, TY = 16, LDX = 132;
    extern __shared__ float smem[];
    float* Cs = smem;              // [128][132]  (cat, later H)
    float* Ws = Cs + BM * LDX;     // [16][129]
    const int tid = threadIdx.x;
    const int tx = tid & 15, ty = tid >> 4;
    const int n0 = blockIdx.x * BM;
    const float gmax = __uint_as_float(g_max_bits);
    const float C = 1e-16f * __expf(8.f * gmax);

    for (int u = tid; u < BM * 128; u += NT) {
        int row = u >> 7;
        int c = u & 127;
        int n = n0 + row;
        float val = 0.f;
        if (n < Nn) {
            if (c < 64) val = 0.125f * __logf(g_exps[(long long)n * 64 + c] + C);
            else        val = __ldg(ns + (long long)n * 64 + (c - 64));
        }
        Cs[row * LDX + c] = val;
    }
    float acc[RI][8];
    #pragma unroll
    for (int i = 0; i < RI; ++i)
        #pragma unroll
        for (int j = 0; j < 8; ++j) acc[i][j] = 0.f;
    gemm_tile<128, LDX, 128, NT, RI>(Cs, Ws, uw1, acc, tid);
    __syncthreads();
    #pragma unroll
    for (int j = 0; j < 8; ++j) {
        int c = tx + 16 * j;
        float bb = __ldg(ub1 + c);
        #pragma unroll
        for (int i = 0; i < RI; ++i) {
            float h = acc[i][j] + bb;
            Cs[(ty + TY * i) * LDX + c] = h > 0.f ? h : 0.f;
        }
    }
    float acc2[RI][4];
    #pragma unroll
    for (int i = 0; i < RI; ++i)
        #pragma unroll
        for (int j = 0; j < 4; ++j) acc2[i][j] = 0.f;
    gemm_tile<128, LDX, 64, NT, RI>(Cs, Ws, uw2, acc2, tid);
    #pragma unroll
    for (int j = 0; j < 4; ++j) {
        int c = tx + 16 * j;
        float bb = __ldg(ub2 + c);
        #pragma unroll
        for (int i = 0; i < RI; ++i) {
            int n = n0 + ty + TY * i;
            if (n < Nn) out[(long long)n * 64 + c] = acc2[i][j] + bb;
        }
    }
}

// ---------------- host ----------------
extern "C" void kernel_launch(void* const* d_in, const int* in_sizes, int n_in,
                              void* d_out, int out_size) {
    const float* ns  = (const float*)d_in[0];
    const void*  i0  = d_in[1];
    const void*  i1  = d_in[2];
    const void*  i2  = d_in[3];
    const float* r0w1 = (const float*)d_in[4];
    const float* r0b1 = (const float*)d_in[5];
    const float* r0w2 = (const float*)d_in[6];
    const float* r0b2 = (const float*)d_in[7];
    const float* r1w1 = (const float*)d_in[8];
    const float* r1b1 = (const float*)d_in[9];
    const float* r1w2 = (const float*)d_in[10];
    const float* r1b2 = (const float*)d_in[11];
    const float* r2w1 = (const float*)d_in[12];
    const float* r2b1 = (const float*)d_in[13];
    const float* r2w2 = (const float*)d_in[14];
    const float* r2b2 = (const float*)d_in[15];
    const float* uw1  = (const float*)d_in[16];
    const float* ub1  = (const float*)d_in[17];
    const float* uw2  = (const float*)d_in[18];
    const float* ub2  = (const float*)d_in[19];
    float* out = (float*)d_out;

    const int T0 = in_sizes[1] / 2;
    const int T1 = in_sizes[2] / 2;
    const int T2 = in_sizes[3] / 3;
    const int Nn = in_sizes[0] / 64;

    // smem sizes (floats): Xs + Ws + red + idx
    const int smem2 = (128 * 132 + 16 * 129 + 8  + 128 * 2) * 4;
    const int smem3 = (128 * 196 + 16 * 193 + 16 + 128 * 3) * 4;
    const int smemU = (128 * 132 + 16 * 129) * 4;

    static bool attr_done = false;
    if (!attr_done) {
        cudaFuncSetAttribute((const void*)rel_kernel<2, 256, 8, 2>,
                             cudaFuncAttributeMaxDynamicSharedMemorySize, smem2);
        cudaFuncSetAttribute((const void*)rel_kernel<3, 512, 4, 1>,
                             cudaFuncAttributeMaxDynamicSharedMemorySize, smem3);
        cudaFuncSetAttribute((const void*)update_kernel,
                             cudaFuncAttributeMaxDynamicSharedMemorySize, smemU);
        attr_done = true;
    }

    detect_kernel<<<1, 32>>>((const int*)i0);
    init_kernel<<<(12800000 / 4 + 255) / 256, 256>>>();

    rel_kernel<2, 256, 8, 2><<<(T0 + 127) / 128, 256, smem2>>>(ns, i0, r0w1, r0b1, r0w2, r0b2, T0);
    rel_kernel<2, 256, 8, 2><<<(T1 + 127) / 128, 256, smem2>>>(ns, i1, r1w1, r1b1, r1w2, r1b2, T1);
    rel_kernel<3, 512, 4, 1><<<(T2 + 127) / 128, 512, smem3>>>(ns, i2, r2w1, r2b1, r2w2, r2b2, T2);

    update_kernel<<<(Nn + 127) / 128, 256, smemU>>>(ns, uw1, ub1, uw2, ub2, out, Nn);
}

// round 10
// speedup vs baseline: 1.0744x; 1.0039x over previous
#include <cuda_runtime.h>
#include <cstdint>

typedef unsigned long long u64_t;

// ---------------- scratch (device globals; no allocation allowed) ----------------
__device__ __align__(16) float g_exps[12800000]; // 200000 * 64  (sum of exp(8*o))
__device__ unsigned g_max_bits;
__device__ int g_idx64;  // 1 if index buffers are int64, 0 if int32

__device__ __forceinline__ void atomicMaxF(float val) {
    if (val >= 0.f) atomicMax((int*)&g_max_bits, __float_as_int(val));
    else            atomicMin(&g_max_bits, (unsigned)__float_as_int(val));
}

__device__ __forceinline__ int load_idx(const void* idx, long long flat, int is64) {
    if (is64) return (int)__ldg(reinterpret_cast<const long long*>(idx) + flat);
    return __ldg(reinterpret_cast<const int*>(idx) + flat);
}

// horizontal sum of packed f32x2
__device__ __forceinline__ float hsum(u64_t v) {
    float lo, hi;
    asm("mov.b64 {%0, %1}, %2;" : "=f"(lo), "=f"(hi) : "l"(v));
    return lo + hi;
}

// ---------------- dtype probe: int64 buffers of small values have zero odd words ----------------
__global__ void detect_kernel(const int* __restrict__ i0) {
    if (threadIdx.x == 0 && blockIdx.x == 0) {
        int is64 = 1;
        #pragma unroll
        for (int k = 1; k < 32; k += 2)
            if (__ldg(i0 + k) != 0) { is64 = 0; break; }
        g_idx64 = is64;
    }
}

// ---------------- packed-f32x2 tiled GEMM core ----------------
// Xs: smem [BM][LDX] row-major X tile. Wg: global [NCOL][K] row-major.
// Ws: smem [NCOL][18] col-major W tile (18-float stride: conflict-free LDS.64).
// acc[i][j] (f32x2) accumulates even-k in .lo, odd-k in .hi for
// row = ty + (NT/32)*i, col = tx + 32*j.  Final value = hsum(acc).
template<int K, int LDX, int NCOL, int NT, int RI>
__device__ __forceinline__ void gemm_tile(const float* __restrict__ Xs,
                                          float* __restrict__ Ws,
                                          const float* __restrict__ Wg,
                                          u64_t (&acc)[RI][NCOL / 32], int tid) {
    const int tx = tid & 31, ty = tid >> 5;
    constexpr int TY = NT / 32;
    constexpr int NJ = NCOL / 32;
    constexpr int LDB = 18;
    for (int k0 = 0; k0 < K; k0 += 16) {
        __syncthreads(); // protect Ws reuse + order producer smem writes
        #pragma unroll
        for (int u = tid; u < 16 * NCOL; u += NT) {
            int j = u >> 4, kk = u & 15;
            Ws[j * LDB + kk] = __ldg(Wg + j * K + k0 + kk);
        }
        __syncthreads();
        #pragma unroll
        for (int kk = 0; kk < 16; kk += 2) {
            u64_t a2[RI], b2[NJ];
            #pragma unroll
            for (int i = 0; i < RI; ++i)
                a2[i] = *reinterpret_cast<const u64_t*>(Xs + (ty + TY * i) * LDX + k0 + kk);
            #pragma unroll
            for (int j = 0; j < NJ; ++j)
                b2[j] = *reinterpret_cast<const u64_t*>(Ws + (tx + 32 * j) * LDB + kk);
            #pragma unroll
            for (int i = 0; i < RI; ++i)
                #pragma unroll
                for (int j = 0; j < NJ; ++j)
                    asm("fma.rn.f32x2 %0, %1, %2, %0;"
                        : "+l"(acc[i][j]) : "l"(a2[i]), "l"(b2[j]));
        }
    }
}

// ---------------- fused per-relation: gather -> MLP -> exp(8*o) scatter-add ----------------
// BM = 64 tuples per block.
template<int A, int NT, int RI, int MINB>
__global__ void __launch_bounds__(NT, MINB)
rel_kernel(const float* __restrict__ ns, const void* __restrict__ idx,
           const float* __restrict__ w1, const float* __restrict__ b1,
           const float* __restrict__ w2, const float* __restrict__ b2,
           int T) {
    constexpr int BM = 64;
    constexpr int D = A * 64;
    constexpr int LDX = D + 4;
    constexpr int NJ = D / 32;
    constexpr int TY = NT / 32;
    constexpr int NW = NT / 32;
    extern __shared__ float smem[];
    float* Xs  = smem;                  // [BM][LDX]  (X, then H, then O)
    float* Ws  = Xs + BM * LDX;         // [D][18] col-major W tile
    float* red = Ws + D * 18;           // [NW]
    int* s_idx = (int*)(red + NW);      // [BM*A]

    const int tid = threadIdx.x;
    const int tx = tid & 31, ty = tid >> 5;
    const int m0 = blockIdx.x * BM;
    const int is64 = g_idx64;

    // cache tuple indices
    for (int e = tid; e < BM * A; e += NT) {
        long long flat = (long long)m0 * A + e;
        s_idx[e] = (flat < (long long)T * A) ? load_idx(idx, flat, is64) : -1;
    }
    __syncthreads();
    // gather: 16 consecutive threads copy one 64-float node row
    for (int u = tid; u < BM * A * 16; u += NT) {
        int pair = u >> 4;           // row*A + slot
        int v = u & 15;
        int row = pair / A;
        int slot = pair - row * A;
        int node = s_idx[pair];
        float4 val = make_float4(0.f, 0.f, 0.f, 0.f);
        if (node >= 0)
            val = __ldg(reinterpret_cast<const float4*>(ns + (long long)node * 64) + v);
        reinterpret_cast<float4*>(Xs + row * LDX + slot * 64)[v] = val;
    }

    u64_t acc[RI][NJ];
    #pragma unroll
    for (int i = 0; i < RI; ++i)
        #pragma unroll
        for (int j = 0; j < NJ; ++j) acc[i][j] = 0ull;

    gemm_tile<D, LDX, D, NT, RI>(Xs, Ws, w1, acc, tid);
    __syncthreads(); // all reads of X done before overwrite with H
    #pragma unroll
    for (int j = 0; j < NJ; ++j) {
        int c = tx + 32 * j;
        float bb = __ldg(b1 + c);
        #pragma unroll
        for (int i = 0; i < RI; ++i) {
            float h = hsum(acc[i][j]) + bb;
            Xs[(ty + TY * i) * LDX + c] = h > 0.f ? h : 0.f;
            acc[i][j] = 0ull;
        }
    }
    gemm_tile<D, LDX, D, NT, RI>(Xs, Ws, w2, acc, tid);
    __syncthreads(); // all reads of H done before overwrite with O

    float lmax = __int_as_float(0xff800000); // -inf
    #pragma unroll
    for (int j = 0; j < NJ; ++j) {
        int c = tx + 32 * j;
        float bb = __ldg(b2 + c);
        #pragma unroll
        for (int i = 0; i < RI; ++i) {
            int m = m0 + ty + TY * i;
            float o = hsum(acc[i][j]) + bb;
            Xs[(ty + TY * i) * LDX + c] = o;
            if (m < T) lmax = fmaxf(lmax, o);
        }
    }
    __syncthreads();

    // vectorized exp + scatter-add of exp(8*o) (no max offset needed: it cancels)
    for (int u = tid; u < BM * A * 16; u += NT) {
        int pair = u >> 4;
        int v = u & 15;
        int node = s_idx[pair];
        if (node < 0) continue;
        int row = pair / A;
        int slot = pair - row * A;
        const float4* src = reinterpret_cast<const float4*>(Xs + row * LDX + slot * 64) + v;
        float4 o4 = *src;
        float4 e;
        e.x = __expf(8.f * o4.x);
        e.y = __expf(8.f * o4.y);
        e.z = __expf(8.f * o4.z);
        e.w = __expf(8.f * o4.w);
        float* p = g_exps + ((long long)node << 6) + (v << 2);
        asm volatile("red.global.add.v4.f32 [%0], {%1,%2,%3,%4};"
                     :: "l"(p), "f"(e.x), "f"(e.y), "f"(e.z), "f"(e.w) : "memory");
    }

    // block max -> single atomic (for the exact 1e-16 floor term later)
    #pragma unroll
    for (int off = 16; off; off >>= 1)
        lmax = fmaxf(lmax, __shfl_xor_sync(0xffffffffu, lmax, off));
    if ((tid & 31) == 0) red[tid >> 5] = lmax;
    __syncthreads();
    if (tid == 0) {
        float v = red[0];
        #pragma unroll
        for (int w = 1; w < NW; ++w) v = fmaxf(v, red[w]);
        atomicMaxF(v);
    }
}

// ---------------- init exps + global max ----------------
__global__ void __launch_bounds__(256) init_kernel() {
    int t = blockIdx.x * 256 + threadIdx.x;
    if (t == 0) g_max_bits = 0xff800000u; // -inf
    if (t < 12800000 / 4)
        reinterpret_cast<float4*>(g_exps)[t] = make_float4(0.f, 0.f, 0.f, 0.f);
}

// ---------------- final update MLP: relu(cat@u_w1^T+b1)@u_w2^T+b2 ----------------
// max_msg = 0.125*log(1e-16*e^{8g} + S) with S = sum exp(8*o)  (exact rewrite of ref)
__global__ void __launch_bounds__(256, 2)
update_kernel(const float* __restrict__ ns,
              const float* __restrict__ uw1, const float* __restrict__ ub1,
              const float* __restrict__ uw2, const float* __restrict__ ub2,
              float* __restrict__ out, int Nn) {
    constexpr int BM = 64, NT = 256, RI = 8, TY = 8, LDX = 132;
    extern __shared__ float smem[];
    float* Cs = smem;              // [64][132]  (cat, later H)
    float* Ws = Cs + BM * LDX;     // [128][18] col-major
    const int tid = threadIdx.x;
    const int tx = tid & 31, ty = tid >> 5;
    const int n0 = blockIdx.x * BM;
    const float gmax = __uint_as_float(g_max_bits);
    const float C = 1e-16f * __expf(8.f * gmax);

    for (int u = tid; u < BM * 128; u += NT) {
        int row = u >> 7;
        int c = u & 127;
        int n = n0 + row;
        float val = 0.f;
        if (n < Nn) {
            if (c < 64) val = 0.125f * __logf(g_exps[(long long)n * 64 + c] + C);
            else        val = __ldg(ns + (long long)n * 64 + (c - 64));
        }
        Cs[row * LDX + c] = val;
    }
    u64_t acc[RI][4];
    #pragma unroll
    for (int i = 0; i < RI; ++i)
        #pragma unroll
        for (int j = 0; j < 4; ++j) acc[i][j] = 0ull;
    gemm_tile<128, LDX, 128, NT, RI>(Cs, Ws, uw1, acc, tid);
    __syncthreads();
    #pragma unroll
    for (int j = 0; j < 4; ++j) {
        int c = tx + 32 * j;
        float bb = __ldg(ub1 + c);
        #pragma unroll
        for (int i = 0; i < RI; ++i) {
            float h = hsum(acc[i][j]) + bb;
            Cs[(ty + TY * i) * LDX + c] = h > 0.f ? h : 0.f;
        }
    }
    u64_t acc2[RI][2];
    #pragma unroll
    for (int i = 0; i < RI; ++i)
        #pragma unroll
        for (int j = 0; j < 2; ++j) acc2[i][j] = 0ull;
    gemm_tile<128, LDX, 64, NT, RI>(Cs, Ws, uw2, acc2, tid);
    #pragma unroll
    for (int j = 0; j < 2; ++j) {
        int c = tx + 32 * j;
        float bb = __ldg(ub2 + c);
        #pragma unroll
        for (int i = 0; i < RI; ++i) {
            int n = n0 + ty + TY * i;
            if (n < Nn) out[(long long)n * 64 + c] = hsum(acc2[i][j]) + bb;
        }
    }
}

// ---------------- host ----------------
extern "C" void kernel_launch(void* const* d_in, const int* in_sizes, int n_in,
                              void* d_out, int out_size) {
    const float* ns  = (const float*)d_in[0];
    const void*  i0  = d_in[1];
    const void*  i1  = d_in[2];
    const void*  i2  = d_in[3];
    const float* r0w1 = (const float*)d_in[4];
    const float* r0b1 = (const float*)d_in[5];
    const float* r0w2 = (const float*)d_in[6];
    const float* r0b2 = (const float*)d_in[7];
    const float* r1w1 = (const float*)d_in[8];
    const float* r1b1 = (const float*)d_in[9];
    const float* r1w2 = (const float*)d_in[10];
    const float* r1b2 = (const float*)d_in[11];
    const float* r2w1 = (const float*)d_in[12];
    const float* r2b1 = (const float*)d_in[13];
    const float* r2w2 = (const float*)d_in[14];
    const float* r2b2 = (const float*)d_in[15];
    const float* uw1  = (const float*)d_in[16];
    const float* ub1  = (const float*)d_in[17];
    const float* uw2  = (const float*)d_in[18];
    const float* ub2  = (const float*)d_in[19];
    float* out = (float*)d_out;

    const int T0 = in_sizes[1] / 2;
    const int T1 = in_sizes[2] / 2;
    const int T2 = in_sizes[3] / 3;
    const int Nn = in_sizes[0] / 64;

    // smem (floats): Xs + Ws + red + idx
    const int smem2 = (64 * 132 + 128 * 18 + 8  + 64 * 2) * 4;
    const int smem3 = (64 * 196 + 192 * 18 + 16 + 64 * 3) * 4;
    const int smemU = (64 * 132 + 128 * 18) * 4;

    static bool attr_done = false;
    if (!attr_done) {
        cudaFuncSetAttribute((const void*)rel_kernel<2, 256, 8, 2>,
                             cudaFuncAttributeMaxDynamicSharedMemorySize, smem2);
        cudaFuncSetAttribute((const void*)rel_kernel<3, 512, 4, 1>,
                             cudaFuncAttributeMaxDynamicSharedMemorySize, smem3);
        cudaFuncSetAttribute((const void*)update_kernel,
                             cudaFuncAttributeMaxDynamicSharedMemorySize, smemU);
        attr_done = true;
    }

    detect_kernel<<<1, 32>>>((const int*)i0);
    init_kernel<<<(12800000 / 4 + 255) / 256, 256>>>();

    rel_kernel<2, 256, 8, 2><<<(T0 + 63) / 64, 256, smem2>>>(ns, i0, r0w1, r0b1, r0w2, r0b2, T0);
    rel_kernel<2, 256, 8, 2><<<(T1 + 63) / 64, 256, smem2>>>(ns, i1, r1w1, r1b1, r1w2, r1b2, T1);
    rel_kernel<3, 512, 4, 1><<<(T2 + 63) / 64, 512, smem3>>>(ns, i2, r2w1, r2b1, r2w2, r2b2, T2);

    update_kernel<<<(Nn + 63) / 64, 256, smemU>>>(ns, uw1, ub1, uw2, ub2, out, Nn);
}